// round 1
// baseline (speedup 1.0000x reference)
#include <cuda_runtime.h>

#define NN 50000
#define NE 800000
#define NV 1000
#define F 128
#define NG 64
#define NC 10

// ---- scratch (no allocations allowed) ----
__device__ float g_tl[NV * F];        // embed_table @ Wl1^T
__device__ float g_tr[NV * F];        // embed_table @ Wr1^T
__device__ float g_h1[NN * F];
__device__ float g_agg[NN * F];
__device__ float g_h2[NN * F];
__device__ float g_pool[NG * F];
__device__ int   g_deg[NN];
__device__ int   g_off[NN + 1];
__device__ int   g_cur[NN];
__device__ int   g_csr[NE];
__device__ int   g_gcnt[NG];

// ---------------- init: zero counters & pool ----------------
__global__ void k_init() {
    int i = blockIdx.x * blockDim.x + threadIdx.x;
    int stride = gridDim.x * blockDim.x;
    for (int x = i; x < NN; x += stride) g_deg[x] = 0;
    for (int x = i; x < NG * F; x += stride) g_pool[x] = 0.f;
    for (int x = i; x < NG; x += stride) g_gcnt[x] = 0;
}

// ---------------- degree & graph-size counts ----------------
__global__ void k_count(const int* __restrict__ dst, const int* __restrict__ batch) {
    int i = blockIdx.x * blockDim.x + threadIdx.x;
    int stride = gridDim.x * blockDim.x;
    for (int e = i; e < NE; e += stride) atomicAdd(&g_deg[dst[e]], 1);
    for (int n = i; n < NN; n += stride) atomicAdd(&g_gcnt[batch[n]], 1);
}

// ---------------- exclusive scan (single block) ----------------
__device__ __forceinline__ int warp_incl_scan(int v) {
    int lane = threadIdx.x & 31;
#pragma unroll
    for (int d = 1; d < 32; d <<= 1) {
        int t = __shfl_up_sync(0xffffffffu, v, d);
        if (lane >= d) v += t;
    }
    return v;
}

__global__ void k_scan() {
    __shared__ int wsum[32];
    __shared__ int carry;
    int t = threadIdx.x, lane = t & 31, w = t >> 5;
    if (t == 0) carry = 0;
    __syncthreads();
    for (int base = 0; base < NN; base += 1024) {
        int i = base + t;
        int v = (i < NN) ? g_deg[i] : 0;
        int incl = warp_incl_scan(v);
        if (lane == 31) wsum[w] = incl;
        __syncthreads();
        if (w == 0) {
            int s = wsum[lane];
            s = warp_incl_scan(s);
            wsum[lane] = s;
        }
        __syncthreads();
        int excl = carry + (w ? wsum[w - 1] : 0) + incl - v;
        if (i < NN) { g_off[i] = excl; g_cur[i] = excl; }
        __syncthreads();
        if (t == 1023) carry += wsum[31];
        __syncthreads();
    }
    if (t == 0) g_off[NN] = carry;
}

// ---------------- CSR fill ----------------
__global__ void k_csr(const int* __restrict__ src, const int* __restrict__ dst) {
    int i = blockIdx.x * blockDim.x + threadIdx.x;
    int stride = gridDim.x * blockDim.x;
    for (int e = i; e < NE; e += stride) {
        int pos = atomicAdd(&g_cur[dst[e]], 1);
        g_csr[pos] = src[e];
    }
}

// ---------------- dual GEMM: Y1 = in1@W1^T, Y2 = in2@W2^T ----------------
// PRE:  write Y1 -> out1, Y2 -> out2  (no bias / relu)
// !PRE: out1 = relu(Y1 + Y2 + bias)
template <bool PRE>
__global__ __launch_bounds__(256)
void k_gemm(const float* in1, const float* in2,
            const float* __restrict__ W1, const float* __restrict__ W2,
            const float* __restrict__ bias,
            float* __restrict__ out1, float* __restrict__ out2, int rows) {
    __shared__ float sA[128 * 33];
    __shared__ float sX[128 * 33];
    const int node0 = blockIdx.x * 32;
    const int t = threadIdx.x;

    // stage 32 rows of in1/in2, transposed (pitch 33 -> conflict-free)
    for (int idx = t; idx < 32 * 128; idx += 256) {
        int n = idx >> 7, k = idx & 127;
        int g = node0 + n;
        float a = 0.f, x = 0.f;
        if (g < rows) {
            a = in1[g * F + k];
            x = in2[g * F + k];
        }
        sA[k * 33 + n] = a;
        sX[k * 33 + n] = x;
    }
    __syncthreads();

    const int lane = t & 31, w = t >> 5;
    const int j0 = w * 16;
    float acc1[16], acc2[16];
#pragma unroll
    for (int jj = 0; jj < 16; jj++) { acc1[jj] = 0.f; acc2[jj] = 0.f; }

#pragma unroll 2
    for (int k0 = 0; k0 < 128; k0 += 4) {
        float a0 = sA[(k0 + 0) * 33 + lane];
        float a1 = sA[(k0 + 1) * 33 + lane];
        float a2 = sA[(k0 + 2) * 33 + lane];
        float a3 = sA[(k0 + 3) * 33 + lane];
        float x0 = sX[(k0 + 0) * 33 + lane];
        float x1 = sX[(k0 + 1) * 33 + lane];
        float x2 = sX[(k0 + 2) * 33 + lane];
        float x3 = sX[(k0 + 3) * 33 + lane];
#pragma unroll
        for (int jj = 0; jj < 16; jj++) {
            const float4 w1 = *reinterpret_cast<const float4*>(&W1[(j0 + jj) * F + k0]);
            acc1[jj] = fmaf(a0, w1.x, fmaf(a1, w1.y, fmaf(a2, w1.z, fmaf(a3, w1.w, acc1[jj]))));
            const float4 w2 = *reinterpret_cast<const float4*>(&W2[(j0 + jj) * F + k0]);
            acc2[jj] = fmaf(x0, w2.x, fmaf(x1, w2.y, fmaf(x2, w2.z, fmaf(x3, w2.w, acc2[jj]))));
        }
    }
    __syncthreads();

    if (PRE) {
#pragma unroll
        for (int jj = 0; jj < 16; jj++) sA[(j0 + jj) * 33 + lane] = acc1[jj];
        __syncthreads();
        for (int idx = t; idx < 32 * 128; idx += 256) {
            int n = idx >> 7, j = idx & 127;
            int g = node0 + n;
            if (g < rows) out1[g * F + j] = sA[j * 33 + n];
        }
        __syncthreads();
#pragma unroll
        for (int jj = 0; jj < 16; jj++) sA[(j0 + jj) * 33 + lane] = acc2[jj];
        __syncthreads();
        for (int idx = t; idx < 32 * 128; idx += 256) {
            int n = idx >> 7, j = idx & 127;
            int g = node0 + n;
            if (g < rows) out2[g * F + j] = sA[j * 33 + n];
        }
    } else {
#pragma unroll
        for (int jj = 0; jj < 16; jj++) {
            float v = acc1[jj] + acc2[jj] + bias[j0 + jj];
            sA[(j0 + jj) * 33 + lane] = fmaxf(v, 0.f);
        }
        __syncthreads();
        for (int idx = t; idx < 32 * 128; idx += 256) {
            int n = idx >> 7, j = idx & 127;
            int g = node0 + n;
            if (g < rows) out1[g * F + j] = sA[j * 33 + n];
        }
    }
}

// ---------------- layer-1 aggregate (fused): h1 = relu(mean(tl[x_idx[src]]) + bl1 + tr[x_idx[n]]) ----------------
__global__ void k_agg1(const int* __restrict__ x_idx, const float* __restrict__ bl1) {
    int gid = blockIdx.x * blockDim.x + threadIdx.x;
    int n = gid >> 5;
    int lane = gid & 31;
    if (n >= NN) return;
    int o0 = g_off[n], o1 = g_off[n + 1];
    const float4* tl4 = reinterpret_cast<const float4*>(g_tl);
    float4 acc = make_float4(0.f, 0.f, 0.f, 0.f);
    int e = o0;
    for (; e + 1 < o1; e += 2) {
        int s0 = g_csr[e], s1 = g_csr[e + 1];
        int v0 = x_idx[s0], v1 = x_idx[s1];
        float4 t0 = tl4[v0 * 32 + lane];
        float4 t1 = tl4[v1 * 32 + lane];
        acc.x += t0.x + t1.x; acc.y += t0.y + t1.y;
        acc.z += t0.z + t1.z; acc.w += t0.w + t1.w;
    }
    if (e < o1) {
        int v = x_idx[g_csr[e]];
        float4 t0 = tl4[v * 32 + lane];
        acc.x += t0.x; acc.y += t0.y; acc.z += t0.z; acc.w += t0.w;
    }
    float inv = 1.f / fmaxf((float)(o1 - o0), 1.f);
    int vs = x_idx[n];
    float4 r = reinterpret_cast<const float4*>(g_tr)[vs * 32 + lane];
    float4 b = reinterpret_cast<const float4*>(bl1)[lane];
    float4 h;
    h.x = fmaxf(acc.x * inv + b.x + r.x, 0.f);
    h.y = fmaxf(acc.y * inv + b.y + r.y, 0.f);
    h.z = fmaxf(acc.z * inv + b.z + r.z, 0.f);
    h.w = fmaxf(acc.w * inv + b.w + r.w, 0.f);
    reinterpret_cast<float4*>(g_h1)[n * 32 + lane] = h;
}

// ---------------- layer-2 aggregate: g_agg = mean over incoming h1 rows ----------------
__global__ void k_agg2() {
    int gid = blockIdx.x * blockDim.x + threadIdx.x;
    int n = gid >> 5;
    int lane = gid & 31;
    if (n >= NN) return;
    int o0 = g_off[n], o1 = g_off[n + 1];
    const float4* h4 = reinterpret_cast<const float4*>(g_h1);
    float4 acc = make_float4(0.f, 0.f, 0.f, 0.f);
    int e = o0;
    for (; e + 1 < o1; e += 2) {
        int s0 = g_csr[e], s1 = g_csr[e + 1];
        float4 t0 = h4[s0 * 32 + lane];
        float4 t1 = h4[s1 * 32 + lane];
        acc.x += t0.x + t1.x; acc.y += t0.y + t1.y;
        acc.z += t0.z + t1.z; acc.w += t0.w + t1.w;
    }
    if (e < o1) {
        float4 t0 = h4[g_csr[e] * 32 + lane];
        acc.x += t0.x; acc.y += t0.y; acc.z += t0.z; acc.w += t0.w;
    }
    float inv = 1.f / fmaxf((float)(o1 - o0), 1.f);
    float4 o;
    o.x = acc.x * inv; o.y = acc.y * inv; o.z = acc.z * inv; o.w = acc.w * inv;
    reinterpret_cast<float4*>(g_agg)[n * 32 + lane] = o;
}

// ---------------- global mean pool (batch is sorted) ----------------
#define POOL_CHUNK 512
__global__ void k_pool(const int* __restrict__ batch) {
    int j = threadIdx.x;                    // feature (128)
    int base = blockIdx.x * POOL_CHUNK;
    if (base >= NN) return;
    int end = min(base + POOL_CHUNK, NN);
    int cur = batch[base];
    float acc = 0.f;
    for (int n = base; n < end; n++) {
        int g = batch[n];
        if (g != cur) {
            atomicAdd(&g_pool[cur * F + j], acc);
            acc = 0.f;
            cur = g;
        }
        acc += g_h2[n * F + j];
    }
    atomicAdd(&g_pool[cur * F + j], acc);
}

// ---------------- classifier: out[g][c] = (pool[g]/cnt[g]) . linW[c] + linb[c] ----------------
__global__ void k_out(const float* __restrict__ linW, const float* __restrict__ linb,
                      float* __restrict__ out) {
    int g = blockIdx.x;
    int c = threadIdx.x >> 5;
    int lane = threadIdx.x & 31;
    if (c >= NC) return;
    float inv = 1.f / fmaxf((float)g_gcnt[g], 1.f);
    float s = 0.f;
    for (int k = lane; k < F; k += 32)
        s += g_pool[g * F + k] * linW[c * F + k];
#pragma unroll
    for (int d = 16; d > 0; d >>= 1) s += __shfl_down_sync(0xffffffffu, s, d);
    if (lane == 0) out[g * NC + c] = s * inv + linb[c];
}

extern "C" void kernel_launch(void* const* d_in, const int* in_sizes, int n_in,
                              void* d_out, int out_size) {
    const int*   x_idx = (const int*)d_in[0];
    const int*   eidx  = (const int*)d_in[1];
    const int*   batch = (const int*)d_in[2];
    const float* table = (const float*)d_in[3];
    const float* Wl1   = (const float*)d_in[4];
    const float* bl1   = (const float*)d_in[5];
    const float* Wr1   = (const float*)d_in[6];
    const float* Wl2   = (const float*)d_in[7];
    const float* bl2   = (const float*)d_in[8];
    const float* Wr2   = (const float*)d_in[9];
    const float* linW  = (const float*)d_in[10];
    const float* linb  = (const float*)d_in[11];
    float* out = (float*)d_out;

    const int* src = eidx;
    const int* dst = eidx + NE;

    float *d_tl, *d_tr;
    cudaGetSymbolAddress((void**)&d_tl, g_tl);
    cudaGetSymbolAddress((void**)&d_tr, g_tr);
    float *d_h1, *d_agg, *d_h2;
    cudaGetSymbolAddress((void**)&d_h1, g_h1);
    cudaGetSymbolAddress((void**)&d_agg, g_agg);
    cudaGetSymbolAddress((void**)&d_h2, g_h2);

    k_init<<<196, 256>>>();
    k_count<<<3125, 256>>>(dst, batch);
    k_scan<<<1, 1024>>>();
    k_csr<<<3125, 256>>>(src, dst);

    // precompute vocab-transformed tables: tl = E@Wl1^T, tr = E@Wr1^T
    k_gemm<true><<<(NV + 31) / 32, 256>>>(table, table, Wl1, Wr1, nullptr, d_tl, d_tr, NV);

    // layer 1 (aggregation fused with pre-transformed tables)
    k_agg1<<<(NN * 32 + 255) / 256, 256>>>(x_idx, bl1);

    // layer 2
    k_agg2<<<(NN * 32 + 255) / 256, 256>>>();
    k_gemm<false><<<(NN + 31) / 32, 256>>>(d_agg, d_h1, Wl2, Wr2, bl2, d_h2, nullptr, NN);

    // pool + classify
    k_pool<<<(NN + POOL_CHUNK - 1) / POOL_CHUNK, 128>>>(batch);
    k_out<<<NG, 320>>>(linW, linb, out);
}

// round 2
// speedup vs baseline: 2.1042x; 2.1042x over previous
#include <cuda_runtime.h>

#define NN 50000
#define NE 800000
#define NV 1000
#define F 128
#define NG 64
#define NC 10
#define NSCANBLK 49

// ---- scratch (no allocations allowed) ----
__device__ float g_tl[NV * F];        // embed_table @ Wl1^T
__device__ float g_tr[NV * F];        // embed_table @ Wr1^T
__device__ float g_h1[NN * F];
__device__ float g_agg[NN * F];
__device__ float g_h2[NN * F];
__device__ float g_pool[NG * F];
__device__ float g_WT[256 * F];       // [Wl2 | Wr2] transposed: WT[k][j]
__device__ int   g_deg[NN];
__device__ int   g_off[NN + 1];
__device__ int   g_cur[NN];
__device__ int   g_csr[NE];           // src node id
__device__ int   g_csrv[NE];          // x_idx[src] (vocab id)
__device__ int   g_gcnt[NG];
__device__ int   g_goff[NG + 1];
__device__ int   g_psum[64];

// ---------------- init: zero counters ----------------
__global__ void k_init() {
    int i = blockIdx.x * blockDim.x + threadIdx.x;
    int stride = gridDim.x * blockDim.x;
    for (int x = i; x < NN; x += stride) g_deg[x] = 0;
    for (int x = i; x < NG; x += stride) g_gcnt[x] = 0;
}

// ---------------- degree & graph-size counts ----------------
__global__ void k_count(const int* __restrict__ dst, const int* __restrict__ batch) {
    int i = blockIdx.x * blockDim.x + threadIdx.x;
    int stride = gridDim.x * blockDim.x;
    for (int e = i; e < NE; e += stride) atomicAdd(&g_deg[dst[e]], 1);
    for (int n = i; n < NN; n += stride) atomicAdd(&g_gcnt[batch[n]], 1);
}

__device__ __forceinline__ int warp_incl_scan(int v) {
    int lane = threadIdx.x & 31;
#pragma unroll
    for (int d = 1; d < 32; d <<= 1) {
        int t = __shfl_up_sync(0xffffffffu, v, d);
        if (lane >= d) v += t;
    }
    return v;
}

// ---------------- multi-block scan, phase 1: per-block ----------------
__global__ void k_scan_blk() {
    __shared__ int wsum[32];
    int t = threadIdx.x, lane = t & 31, w = t >> 5;
    int i = blockIdx.x * 1024 + t;
    int v = (i < NN) ? g_deg[i] : 0;
    int incl = warp_incl_scan(v);
    if (lane == 31) wsum[w] = incl;
    __syncthreads();
    if (w == 0) wsum[lane] = warp_incl_scan(wsum[lane]);
    __syncthreads();
    int excl = (w ? wsum[w - 1] : 0) + incl - v;
    if (i < NN) g_off[i] = excl;
    if (t == 1023) g_psum[blockIdx.x] = wsum[31];
}

// ---------------- phase 2: scan partials (warp0) + graph offsets (warp1) ----------------
__global__ void k_scan_top() {
    int t = threadIdx.x, lane = t & 31;
    if (t < 32) {
        int carry = 0;
        for (int base = 0; base < NSCANBLK; base += 32) {
            int i = base + lane;
            int v = (i < NSCANBLK) ? g_psum[i] : 0;
            int incl = warp_incl_scan(v);
            if (i < NSCANBLK) g_psum[i] = carry + incl - v;
            carry += __shfl_sync(0xffffffffu, incl, 31);
        }
    } else {
        int carry = 0;
        for (int base = 0; base < NG; base += 32) {
            int i = base + lane;
            int v = g_gcnt[i];
            int incl = warp_incl_scan(v);
            g_goff[i] = carry + incl - v;
            carry += __shfl_sync(0xffffffffu, incl, 31);
        }
        if (lane == 0) g_goff[NG] = NN;
    }
}

// ---------------- phase 3: add block prefixes ----------------
__global__ void k_scan_add() {
    int t = threadIdx.x;
    int i = blockIdx.x * 1024 + t;
    if (i < NN) {
        int o = g_off[i] + g_psum[blockIdx.x];
        g_off[i] = o;
        g_cur[i] = o;
    }
    if (i == 0) g_off[NN] = NE;
}

// ---------------- CSR fill (resolve vocab id here) ----------------
__global__ void k_csr(const int* __restrict__ src, const int* __restrict__ dst,
                      const int* __restrict__ x_idx) {
    int i = blockIdx.x * blockDim.x + threadIdx.x;
    int stride = gridDim.x * blockDim.x;
    for (int e = i; e < NE; e += stride) {
        int s = src[e];
        int pos = atomicAdd(&g_cur[dst[e]], 1);
        g_csr[pos] = s;
        g_csrv[pos] = x_idx[s];
    }
}

// ---------------- transpose weights: WT[k][j] = (k<128 ? Wl2 : Wr2)[j][k&127] ----------------
__global__ void k_wt(const float* __restrict__ Wl2, const float* __restrict__ Wr2) {
    int idx = blockIdx.x * 256 + threadIdx.x;       // 0..32767
    int k = idx >> 7, j = idx & 127;
    g_WT[idx] = (k < 128) ? Wl2[j * F + k] : Wr2[j * F + (k - 128)];
}

// ---------------- small dual GEMM (vocab tables): Y1=in@W1^T, Y2=in@W2^T ----------------
__global__ __launch_bounds__(256)
void k_gemm_pre(const float* __restrict__ in,
                const float* __restrict__ W1, const float* __restrict__ W2,
                float* __restrict__ out1, float* __restrict__ out2, int rows) {
    __shared__ float sA[128 * 33];
    const int node0 = blockIdx.x * 32;
    const int t = threadIdx.x;
    for (int idx = t; idx < 32 * 128; idx += 256) {
        int n = idx >> 7, k = idx & 127;
        int g = node0 + n;
        sA[k * 33 + n] = (g < rows) ? in[g * F + k] : 0.f;
    }
    __syncthreads();
    const int lane = t & 31, w = t >> 5;
    const int j0 = w * 16;
    float acc1[16], acc2[16];
#pragma unroll
    for (int jj = 0; jj < 16; jj++) { acc1[jj] = 0.f; acc2[jj] = 0.f; }
#pragma unroll 2
    for (int k0 = 0; k0 < 128; k0 += 4) {
        float a0 = sA[(k0 + 0) * 33 + lane];
        float a1 = sA[(k0 + 1) * 33 + lane];
        float a2 = sA[(k0 + 2) * 33 + lane];
        float a3 = sA[(k0 + 3) * 33 + lane];
#pragma unroll
        for (int jj = 0; jj < 16; jj++) {
            const float4 w1 = *reinterpret_cast<const float4*>(&W1[(j0 + jj) * F + k0]);
            acc1[jj] = fmaf(a0, w1.x, fmaf(a1, w1.y, fmaf(a2, w1.z, fmaf(a3, w1.w, acc1[jj]))));
            const float4 w2 = *reinterpret_cast<const float4*>(&W2[(j0 + jj) * F + k0]);
            acc2[jj] = fmaf(a0, w2.x, fmaf(a1, w2.y, fmaf(a2, w2.z, fmaf(a3, w2.w, acc2[jj]))));
        }
    }
    const int node = node0 + lane;
    if (node < rows) {
#pragma unroll
        for (int jj = 0; jj < 16; jj++) {
            out1[node * F + j0 + jj] = acc1[jj];
            out2[node * F + j0 + jj] = acc2[jj];
        }
    }
}

// ---------------- layer-1: h1 = relu(mean(tl[csrv]) + bl1 + tr[x_idx[n]]) ----------------
__global__ void k_agg1(const int* __restrict__ x_idx, const float* __restrict__ bl1) {
    int gid = blockIdx.x * blockDim.x + threadIdx.x;
    int n = gid >> 5;
    int lane = gid & 31;
    if (n >= NN) return;
    int o0 = g_off[n], o1 = g_off[n + 1];
    const float4* tl4 = reinterpret_cast<const float4*>(g_tl);
    float4 acc = make_float4(0.f, 0.f, 0.f, 0.f);
    int e = o0;
    for (; e + 3 < o1; e += 4) {
        int v0 = g_csrv[e], v1 = g_csrv[e + 1], v2 = g_csrv[e + 2], v3 = g_csrv[e + 3];
        float4 t0 = tl4[v0 * 32 + lane];
        float4 t1 = tl4[v1 * 32 + lane];
        float4 t2 = tl4[v2 * 32 + lane];
        float4 t3 = tl4[v3 * 32 + lane];
        acc.x += (t0.x + t1.x) + (t2.x + t3.x);
        acc.y += (t0.y + t1.y) + (t2.y + t3.y);
        acc.z += (t0.z + t1.z) + (t2.z + t3.z);
        acc.w += (t0.w + t1.w) + (t2.w + t3.w);
    }
    for (; e < o1; e++) {
        float4 t0 = tl4[g_csrv[e] * 32 + lane];
        acc.x += t0.x; acc.y += t0.y; acc.z += t0.z; acc.w += t0.w;
    }
    float inv = 1.f / fmaxf((float)(o1 - o0), 1.f);
    int vs = x_idx[n];
    float4 r = reinterpret_cast<const float4*>(g_tr)[vs * 32 + lane];
    float4 b = reinterpret_cast<const float4*>(bl1)[lane];
    float4 h;
    h.x = fmaxf(fmaf(acc.x, inv, b.x + r.x), 0.f);
    h.y = fmaxf(fmaf(acc.y, inv, b.y + r.y), 0.f);
    h.z = fmaxf(fmaf(acc.z, inv, b.z + r.z), 0.f);
    h.w = fmaxf(fmaf(acc.w, inv, b.w + r.w), 0.f);
    reinterpret_cast<float4*>(g_h1)[n * 32 + lane] = h;
}

// ---------------- layer-2 aggregate: g_agg = mean over incoming h1 rows ----------------
__global__ void k_agg2() {
    int gid = blockIdx.x * blockDim.x + threadIdx.x;
    int n = gid >> 5;
    int lane = gid & 31;
    if (n >= NN) return;
    int o0 = g_off[n], o1 = g_off[n + 1];
    const float4* h4 = reinterpret_cast<const float4*>(g_h1);
    float4 acc = make_float4(0.f, 0.f, 0.f, 0.f);
    int e = o0;
    for (; e + 3 < o1; e += 4) {
        int s0 = g_csr[e], s1 = g_csr[e + 1], s2 = g_csr[e + 2], s3 = g_csr[e + 3];
        float4 t0 = h4[s0 * 32 + lane];
        float4 t1 = h4[s1 * 32 + lane];
        float4 t2 = h4[s2 * 32 + lane];
        float4 t3 = h4[s3 * 32 + lane];
        acc.x += (t0.x + t1.x) + (t2.x + t3.x);
        acc.y += (t0.y + t1.y) + (t2.y + t3.y);
        acc.z += (t0.z + t1.z) + (t2.z + t3.z);
        acc.w += (t0.w + t1.w) + (t2.w + t3.w);
    }
    for (; e < o1; e++) {
        float4 t0 = h4[g_csr[e] * 32 + lane];
        acc.x += t0.x; acc.y += t0.y; acc.z += t0.z; acc.w += t0.w;
    }
    float inv = 1.f / fmaxf((float)(o1 - o0), 1.f);
    float4 o;
    o.x = acc.x * inv; o.y = acc.y * inv; o.z = acc.z * inv; o.w = acc.w * inv;
    reinterpret_cast<float4*>(g_agg)[n * 32 + lane] = o;
}

// ---------------- main GEMM: h2 = relu([agg|h1] @ WT + bl2) ----------------
// M=NN, N=128, K=256. BM=128, BN=128, BK=8. 256 threads, 8x8 per thread.
__global__ __launch_bounds__(256, 2)
void k_gemm2(const float* __restrict__ A1, const float* __restrict__ A2,
             const float* __restrict__ bias, float* __restrict__ out) {
    __shared__ float sA[8][132];
    __shared__ float sB[8][128];
    const int t = threadIdx.x;
    const int node0 = blockIdx.x * 128;
    const int tx = t & 15, ty = t >> 4;
    float acc[8][8];
#pragma unroll
    for (int i = 0; i < 8; i++)
#pragma unroll
        for (int j = 0; j < 8; j++) acc[i][j] = 0.f;

    const int ar = t >> 1;                 // 0..127 node row within tile
    const int akq = (t & 1) * 4;           // k quad within BK
    const int an = node0 + ar;
    const bool avalid = an < NN;
    const int bofs = t * 4;                // B copy: k=bofs>>7, j=bofs&127

    for (int k0 = 0; k0 < 256; k0 += 8) {
        const float* Asrc = (k0 < 128) ? A1 : A2;
        int kk = (k0 & 127) + akq;
        float4 av = make_float4(0.f, 0.f, 0.f, 0.f);
        if (avalid) av = *reinterpret_cast<const float4*>(&Asrc[an * F + kk]);
        sA[akq + 0][ar] = av.x;
        sA[akq + 1][ar] = av.y;
        sA[akq + 2][ar] = av.z;
        sA[akq + 3][ar] = av.w;
        *reinterpret_cast<float4*>(&sB[bofs >> 7][bofs & 127]) =
            *reinterpret_cast<const float4*>(&g_WT[(k0 + (bofs >> 7)) * F + (bofs & 127)]);
        __syncthreads();
#pragma unroll
        for (int kk2 = 0; kk2 < 8; kk2++) {
            float a[8], b[8];
            *(float4*)&a[0] = *(float4*)&sA[kk2][ty * 8];
            *(float4*)&a[4] = *(float4*)&sA[kk2][ty * 8 + 4];
            *(float4*)&b[0] = *(float4*)&sB[kk2][tx * 8];
            *(float4*)&b[4] = *(float4*)&sB[kk2][tx * 8 + 4];
#pragma unroll
            for (int i = 0; i < 8; i++)
#pragma unroll
                for (int j = 0; j < 8; j++)
                    acc[i][j] = fmaf(a[i], b[j], acc[i][j]);
        }
        __syncthreads();
    }
    float bj[8];
    *(float4*)&bj[0] = *(const float4*)&bias[tx * 8];
    *(float4*)&bj[4] = *(const float4*)&bias[tx * 8 + 4];
#pragma unroll
    for (int i = 0; i < 8; i++) {
        int n = node0 + ty * 8 + i;
        if (n < NN) {
            float4 o0, o1;
            o0.x = fmaxf(acc[i][0] + bj[0], 0.f);
            o0.y = fmaxf(acc[i][1] + bj[1], 0.f);
            o0.z = fmaxf(acc[i][2] + bj[2], 0.f);
            o0.w = fmaxf(acc[i][3] + bj[3], 0.f);
            o1.x = fmaxf(acc[i][4] + bj[4], 0.f);
            o1.y = fmaxf(acc[i][5] + bj[5], 0.f);
            o1.z = fmaxf(acc[i][6] + bj[6], 0.f);
            o1.w = fmaxf(acc[i][7] + bj[7], 0.f);
            *reinterpret_cast<float4*>(&out[n * F + tx * 8]) = o0;
            *reinterpret_cast<float4*>(&out[n * F + tx * 8 + 4]) = o1;
        }
    }
}

// ---------------- per-graph mean pool (parallel, no atomics) ----------------
__global__ void k_pool2() {
    __shared__ float4 red[8][32];
    int g = blockIdx.x;
    int s = g_goff[g], e = g_goff[g + 1];
    int lane = threadIdx.x & 31, w = threadIdx.x >> 5;
    const float4* h4 = reinterpret_cast<const float4*>(g_h2);
    float4 acc = make_float4(0.f, 0.f, 0.f, 0.f);
    for (int n = s + w; n < e; n += 8) {
        float4 v = h4[n * 32 + lane];
        acc.x += v.x; acc.y += v.y; acc.z += v.z; acc.w += v.w;
    }
    red[w][lane] = acc;
    __syncthreads();
    if (w == 0) {
        float4 a = red[0][lane];
#pragma unroll
        for (int i = 1; i < 8; i++) {
            float4 b = red[i][lane];
            a.x += b.x; a.y += b.y; a.z += b.z; a.w += b.w;
        }
        float inv = 1.f / fmaxf((float)(e - s), 1.f);
        a.x *= inv; a.y *= inv; a.z *= inv; a.w *= inv;
        reinterpret_cast<float4*>(g_pool)[g * 32 + lane] = a;
    }
}

// ---------------- classifier ----------------
__global__ void k_out(const float* __restrict__ linW, const float* __restrict__ linb,
                      float* __restrict__ out) {
    int g = blockIdx.x;
    int c = threadIdx.x >> 5;
    int lane = threadIdx.x & 31;
    if (c >= NC) return;
    float s = 0.f;
    for (int k = lane; k < F; k += 32)
        s += g_pool[g * F + k] * linW[c * F + k];
#pragma unroll
    for (int d = 16; d > 0; d >>= 1) s += __shfl_down_sync(0xffffffffu, s, d);
    if (lane == 0) out[g * NC + c] = s + linb[c];
}

extern "C" void kernel_launch(void* const* d_in, const int* in_sizes, int n_in,
                              void* d_out, int out_size) {
    const int*   x_idx = (const int*)d_in[0];
    const int*   eidx  = (const int*)d_in[1];
    const int*   batch = (const int*)d_in[2];
    const float* table = (const float*)d_in[3];
    const float* Wl1   = (const float*)d_in[4];
    const float* bl1   = (const float*)d_in[5];
    const float* Wr1   = (const float*)d_in[6];
    const float* Wl2   = (const float*)d_in[7];
    const float* bl2   = (const float*)d_in[8];
    const float* Wr2   = (const float*)d_in[9];
    const float* linW  = (const float*)d_in[10];
    const float* linb  = (const float*)d_in[11];
    float* out = (float*)d_out;

    const int* src = eidx;
    const int* dst = eidx + NE;

    float *d_tl, *d_tr, *d_h1, *d_agg, *d_h2;
    cudaGetSymbolAddress((void**)&d_tl, g_tl);
    cudaGetSymbolAddress((void**)&d_tr, g_tr);
    cudaGetSymbolAddress((void**)&d_h1, g_h1);
    cudaGetSymbolAddress((void**)&d_agg, g_agg);
    cudaGetSymbolAddress((void**)&d_h2, g_h2);

    k_init<<<196, 256>>>();
    k_count<<<3125, 256>>>(dst, batch);
    k_scan_blk<<<NSCANBLK, 1024>>>();
    k_scan_top<<<1, 64>>>();
    k_scan_add<<<NSCANBLK, 1024>>>();
    k_csr<<<3125, 256>>>(src, dst, x_idx);

    // weight prep (independent of graph work)
    k_wt<<<128, 256>>>(Wl2, Wr2);
    k_gemm_pre<<<(NV + 31) / 32, 256>>>(table, Wl1, Wr1, d_tl, d_tr, NV);

    // layer 1
    k_agg1<<<(NN * 32 + 255) / 256, 256>>>(x_idx, bl1);

    // layer 2
    k_agg2<<<(NN * 32 + 255) / 256, 256>>>();
    k_gemm2<<<(NN + 127) / 128, 256>>>(d_agg, d_h1, bl2, d_h2);

    // pool + classify
    k_pool2<<<NG, 256>>>();
    k_out<<<NG, 320>>>(linW, linb, out);
}